// round 15
// baseline (speedup 1.0000x reference)
#include <cuda_runtime.h>

// EdgeUpdateNetwork: T=8, N=256, F=128
//
// Factorization: y[t,i,j,f] = A[t,i,f] + B[t,j,f] where
//   A = x @ w[:, :F]^T,  B = x @ w[:, F:]^T
// BN stats fused into the gemm epilogue (per-block column partials, no
// atomics, deterministic); tiny fold kernel produces scale/shift; then the
// fused affine+relu+diag-zero+L1-normalize streaming kernel writes 537MB.

#define T_DIM 8
#define N_DIM 256
#define F_DIM 128
#define M_DIM (T_DIM * N_DIM)   // 2048 rows
#define O_DIM 512               // A1 | B1 | A2 | B2

// Scratch (device globals — no allocation allowed)
__device__ float g_Y[M_DIM * O_DIM];     // 4 MB: Y[m][o]
__device__ float g_sh[4 * F_DIM];        // [br*256+f]=scale, [br*256+128+f]=shift
__device__ float g_psum[O_DIM * 32];     // [o][mtile] per-tile column sums
__device__ float g_psq [O_DIM * 32];     // [o][mtile] per-tile column sum-sq

// ---------------------------------------------------------------------------
// Kernel 1: X[2048,128] @ W^T[128,512] -> Y[2048,512]
// 64x64 tile, 256 threads (8 warps), 4x4 micro-tile, grid (8,32)=256 blocks.
// Double-buffered smem: ONE __syncthreads per K-chunk. (Measured-best core.)
// Epilogue: per-column sum & sum-of-squares over the tile's 64 rows ->
// g_psum/g_psq[o][mtile]. Each tile lies within one t (256 rows/t = 4 tiles).
// ---------------------------------------------------------------------------
__global__ void __launch_bounds__(256) gemm_kernel(const float* __restrict__ X,
                                                   const float* __restrict__ w1,
                                                   const float* __restrict__ w2) {
    __shared__ float Xs[2][16][68];   // [buf][kk][m]
    __shared__ float Ws[2][16][68];   // [buf][kk][o]
    __shared__ float Ps[64][17];      // [o][ty] column-sum partials
    __shared__ float Qs[64][17];      // [o][ty] column-sumsq partials

    const int m0 = blockIdx.y * 64;
    const int o0 = blockIdx.x * 64;
    const int tid = threadIdx.x;
    const int tx = tid & 15;          // o: cols tx*4 .. tx*4+3
    const int ty = tid >> 4;          // m: rows ty*4 .. ty*4+3 (ty 0..15)
    const float* wbase = (o0 < 256) ? w1 : w2;   // o0 mult of 64, never straddles

    // Per-chunk loads: X tile 64x16 = 256 float4, 1 per thread; W likewise.
    const int xr = tid >> 2, xq = tid & 3;                 // row 0..63, quad 0..3
    const float* xp = X + (m0 + xr) * 128 + xq * 4;
    const float* wp = wbase + ((o0 + xr) & 127) * 256 + (((o0 + xr) >> 7) & 1) * 128 + xq * 4;

    float acc[4][4] = {};
    float4 px, pw;

    // prefetch chunk 0 and stage into buffer 0
    px = *(const float4*)&xp[0];
    pw = *(const float4*)&wp[0];
    Xs[0][xq * 4 + 0][xr] = px.x;  Xs[0][xq * 4 + 1][xr] = px.y;
    Xs[0][xq * 4 + 2][xr] = px.z;  Xs[0][xq * 4 + 3][xr] = px.w;
    Ws[0][xq * 4 + 0][xr] = pw.x;  Ws[0][xq * 4 + 1][xr] = pw.y;
    Ws[0][xq * 4 + 2][xr] = pw.z;  Ws[0][xq * 4 + 3][xr] = pw.w;
    __syncthreads();

    #pragma unroll
    for (int c = 0; c < 8; c++) {
        const int cur = c & 1, nxt = cur ^ 1;
        if (c < 7) {
            const int kc = (c + 1) * 16;
            px = *(const float4*)&xp[kc];
            pw = *(const float4*)&wp[kc];
        }

        #pragma unroll
        for (int kk = 0; kk < 16; kk++) {
            const float4 xa = *(const float4*)&Xs[cur][kk][ty * 4];
            const float4 wr = *(const float4*)&Ws[cur][kk][tx * 4];
            const float xv[4] = {xa.x, xa.y, xa.z, xa.w};
            const float wv[4] = {wr.x, wr.y, wr.z, wr.w};
            #pragma unroll
            for (int a = 0; a < 4; a++)
                #pragma unroll
                for (int b = 0; b < 4; b++)
                    acc[a][b] = fmaf(xv[a], wv[b], acc[a][b]);
        }

        if (c < 7) {
            // Writing the OTHER buffer: safe while peers read `cur`.
            Xs[nxt][xq * 4 + 0][xr] = px.x;  Xs[nxt][xq * 4 + 1][xr] = px.y;
            Xs[nxt][xq * 4 + 2][xr] = px.z;  Xs[nxt][xq * 4 + 3][xr] = px.w;
            Ws[nxt][xq * 4 + 0][xr] = pw.x;  Ws[nxt][xq * 4 + 1][xr] = pw.y;
            Ws[nxt][xq * 4 + 2][xr] = pw.z;  Ws[nxt][xq * 4 + 3][xr] = pw.w;
            __syncthreads();
        }
    }

    #pragma unroll
    for (int a = 0; a < 4; a++) {
        float4 v = make_float4(acc[a][0], acc[a][1], acc[a][2], acc[a][3]);
        *(float4*)&g_Y[(m0 + ty * 4 + a) * O_DIM + o0 + tx * 4] = v;
    }

    // ---- BN stat partials: per-column sum & sumsq over this tile's rows ----
    #pragma unroll
    for (int b = 0; b < 4; b++) {
        const float s = (acc[0][b] + acc[1][b]) + (acc[2][b] + acc[3][b]);
        const float q = fmaf(acc[0][b], acc[0][b],
                        fmaf(acc[1][b], acc[1][b],
                        fmaf(acc[2][b], acc[2][b], acc[3][b] * acc[3][b])));
        Ps[tx * 4 + b][ty] = s;
        Qs[tx * 4 + b][ty] = q;
    }
    __syncthreads();
    if (tid < 64) {
        float s = 0.f, q = 0.f;
        #pragma unroll
        for (int k = 0; k < 16; k++) { s += Ps[tid][k]; q += Qs[tid][k]; }
        g_psum[(o0 + tid) * 32 + blockIdx.y] = s;
        g_psq [(o0 + tid) * 32 + blockIdx.y] = q;
    }
}

// ---------------------------------------------------------------------------
// Kernel 2: fold. 1 block x 256 threads; thread = (br, f).
// Combines 32 per-tile partials per column; per-t sums (4 tiles each) give
// the cross term. Closed form:
//   mean = (sumA + sumB)/2048
//   E[y^2] = (256*(sqA + sqB) + 2*sum_t SA_t*SB_t)/524288
//   s = g * rsqrt(var+eps), h = b - mean*s
// ---------------------------------------------------------------------------
__global__ void __launch_bounds__(256) fold_kernel(const float* __restrict__ gamma1,
                                                   const float* __restrict__ beta1,
                                                   const float* __restrict__ gamma2,
                                                   const float* __restrict__ beta2) {
    const int tid = threadIdx.x;
    const int br = tid >> 7, f = tid & 127;
    const int colA = br * 256 + f, colB = colA + 128;

    float SA[8], SB[8];
    float sqA = 0.f, sqB = 0.f;
    #pragma unroll
    for (int t = 0; t < 8; t++) {
        float sa = 0.f, sb = 0.f;
        #pragma unroll
        for (int k = 0; k < 4; k++) {
            const int mt = t * 4 + k;
            sa  += g_psum[colA * 32 + mt];
            sb  += g_psum[colB * 32 + mt];
            sqA += g_psq [colA * 32 + mt];
            sqB += g_psq [colB * 32 + mt];
        }
        SA[t] = sa;  SB[t] = sb;
    }
    float sumA = 0.f, sumB = 0.f, cross = 0.f;
    #pragma unroll
    for (int t = 0; t < 8; t++) {
        sumA += SA[t];  sumB += SB[t];
        cross = fmaf(SA[t], SB[t], cross);
    }
    const float mean = (sumA + sumB) * (1.0f / 2048.0f);
    const float ey2  = (256.0f * (sqA + sqB) + 2.0f * cross) * (1.0f / 524288.0f);
    const float var  = ey2 - mean * mean;
    const float g  = br ? gamma2[f] : gamma1[f];
    const float bb = br ? beta2[f]  : beta1[f];
    const float s  = g * rsqrtf(var + 1e-5f);
    g_sh[br * 256 + f]       = s;
    g_sh[br * 256 + 128 + f] = bb - mean * s;
}

// ---------------------------------------------------------------------------
// Kernel 3: streaming epilogue (write-bound, 537 MB).
// 2048 blocks x 128 threads: block = (t, br, 8-row i-tile, j-quarter);
// 2048/148 = 13.8 blocks/SM -> ~1% wave tail. Warp w handles 16 j's;
// j OUTER, i inner: each b4 load reused for 8 i-rows, p[ii]=fma(a,s,h)
// in registers. Streaming stores (__stcs).
// ---------------------------------------------------------------------------
__global__ void __launch_bounds__(128) edge_kernel(float* __restrict__ out) {
    const int bid = blockIdx.x;          // 2048 blocks
    const int jq = bid & 3;
    const int itile = (bid >> 2) & 31;
    const int br = (bid >> 7) & 1;
    const int t = bid >> 8;
    const int i0 = itile * 8;
    const int tid = threadIdx.x;
    const int w = tid >> 5, l = tid & 31;
    const int f0 = l * 4;
    const int j0 = jq * 64 + w * 16;

    const float4 s4 = *(const float4*)&g_sh[br * 256 + f0];
    const float4 h4 = *(const float4*)&g_sh[br * 256 + 128 + f0];
    const int baseA = br * 256 + f0;
    const int baseB = baseA + 128;

    float4 p[8];
    #pragma unroll
    for (int ii = 0; ii < 8; ii++) {
        const float4 a4 = *(const float4*)&g_Y[(t * 256 + i0 + ii) * O_DIM + baseA];
        p[ii].x = fmaf(a4.x, s4.x, h4.x);
        p[ii].y = fmaf(a4.y, s4.y, h4.y);
        p[ii].z = fmaf(a4.z, s4.z, h4.z);
        p[ii].w = fmaf(a4.w, s4.w, h4.w);
    }

    // out index: (((t*2+br)*256 + i) * 256 + j) * 128 + f
    const size_t outbase = (size_t)((t * 2 + br) * 256 + i0) * (256 * 128);

    #pragma unroll 2
    for (int jj = 0; jj < 16; jj++) {
        const int j = j0 + jj;
        const float4 b4 = *(const float4*)&g_Y[(t * 256 + j) * O_DIM + baseB];
        float* orow = out + outbase + (size_t)j * 128 + f0;
        #pragma unroll
        for (int ii = 0; ii < 8; ii++) {
            float vx = fmaxf(fmaf(b4.x, s4.x, p[ii].x), 0.0f);
            float vy = fmaxf(fmaf(b4.y, s4.y, p[ii].y), 0.0f);
            float vz = fmaxf(fmaf(b4.z, s4.z, p[ii].z), 0.0f);
            float vw = fmaxf(fmaf(b4.w, s4.w, p[ii].w), 0.0f);
            if (j == i0 + ii) { vx = 0.f; vy = 0.f; vz = 0.f; vw = 0.f; }
            float sm = (vx + vy) + (vz + vw);
            #pragma unroll
            for (int off = 16; off; off >>= 1)
                sm += __shfl_xor_sync(0xffffffffu, sm, off);
            const float inv = __fdividef(1.0f, fmaxf(sm, 1e-12f));
            float4 o4 = make_float4(vx * inv, vy * inv, vz * inv, vw * inv);
            __stcs((float4*)(orow + (size_t)ii * (256 * 128)), o4);
        }
    }
}

// ---------------------------------------------------------------------------
extern "C" void kernel_launch(void* const* d_in, const int* in_sizes, int n_in,
                              void* d_out, int out_size) {
    const float* x  = (const float*)d_in[0];   // node_feats [8,256,128]
    const float* w1 = (const float*)d_in[1];   // [128,256]
    const float* g1 = (const float*)d_in[2];
    const float* b1 = (const float*)d_in[3];
    const float* w2 = (const float*)d_in[4];
    const float* g2 = (const float*)d_in[5];
    const float* b2 = (const float*)d_in[6];
    float* out = (float*)d_out;                // [8,2,256,256,128] fp32

    dim3 ggrid(O_DIM / 64, M_DIM / 64);        // (8, 32) = 256 blocks
    gemm_kernel<<<ggrid, 256>>>(x, w1, w2);
    fold_kernel<<<1, 256>>>(g1, b1, g2, b2);
    edge_kernel<<<2048, 128>>>(out);
}

// round 16
// speedup vs baseline: 1.1412x; 1.1412x over previous
#include <cuda_runtime.h>

// EdgeUpdateNetwork: T=8, N=256, F=128
//
// Factorization: y[t,i,j,f] = A[t,i,f] + B[t,j,f] where
//   A = x @ w[:, :F]^T,  B = x @ w[:, F:]^T
// BN stats in closed form from A/B reductions; then fused
// affine+relu+diag-zero+L1-normalize streaming kernel writes 537MB.

#define T_DIM 8
#define N_DIM 256
#define F_DIM 128
#define M_DIM (T_DIM * N_DIM)   // 2048 rows
#define O_DIM 512               // A1 | B1 | A2 | B2

// Scratch (device globals — no allocation allowed)
__device__ float g_Y[M_DIM * O_DIM];   // 4 MB: Y[m][o]
__device__ float g_sh[4 * F_DIM];      // [br*256 + f] = scale, [br*256+128+f] = shift

// ---------------------------------------------------------------------------
// Kernel 1: X[2048,128] @ W^T[128,512] -> Y[2048,512]
// 64x64 tile, 256 threads (8 warps), 4x4 micro-tile, grid (8,32)=256 blocks.
// Double-buffered smem: ONE __syncthreads per K-chunk. (Measured best: 12.6us)
// ---------------------------------------------------------------------------
__global__ void __launch_bounds__(256) gemm_kernel(const float* __restrict__ X,
                                                   const float* __restrict__ w1,
                                                   const float* __restrict__ w2) {
    __shared__ float Xs[2][16][68];   // [buf][kk][m]
    __shared__ float Ws[2][16][68];   // [buf][kk][o]

    const int m0 = blockIdx.y * 64;
    const int o0 = blockIdx.x * 64;
    const int tid = threadIdx.x;
    const int tx = tid & 15;          // o: cols tx*4 .. tx*4+3
    const int ty = tid >> 4;          // m: rows ty*4 .. ty*4+3 (ty 0..15)
    const float* wbase = (o0 < 256) ? w1 : w2;   // o0 mult of 64, never straddles

    // Per-chunk loads: X tile 64x16 = 256 float4, 1 per thread; W likewise.
    const int xr = tid >> 2, xq = tid & 3;                 // row 0..63, quad 0..3
    const float* xp = X + (m0 + xr) * 128 + xq * 4;
    const float* wp = wbase + ((o0 + xr) & 127) * 256 + (((o0 + xr) >> 7) & 1) * 128 + xq * 4;

    float acc[4][4] = {};
    float4 px, pw;

    // prefetch chunk 0 and stage into buffer 0
    px = *(const float4*)&xp[0];
    pw = *(const float4*)&wp[0];
    Xs[0][xq * 4 + 0][xr] = px.x;  Xs[0][xq * 4 + 1][xr] = px.y;
    Xs[0][xq * 4 + 2][xr] = px.z;  Xs[0][xq * 4 + 3][xr] = px.w;
    Ws[0][xq * 4 + 0][xr] = pw.x;  Ws[0][xq * 4 + 1][xr] = pw.y;
    Ws[0][xq * 4 + 2][xr] = pw.z;  Ws[0][xq * 4 + 3][xr] = pw.w;
    __syncthreads();

    #pragma unroll
    for (int c = 0; c < 8; c++) {
        const int cur = c & 1, nxt = cur ^ 1;
        if (c < 7) {
            const int kc = (c + 1) * 16;
            px = *(const float4*)&xp[kc];
            pw = *(const float4*)&wp[kc];
        }

        #pragma unroll
        for (int kk = 0; kk < 16; kk++) {
            const float4 xa = *(const float4*)&Xs[cur][kk][ty * 4];
            const float4 wr = *(const float4*)&Ws[cur][kk][tx * 4];
            const float xv[4] = {xa.x, xa.y, xa.z, xa.w};
            const float wv[4] = {wr.x, wr.y, wr.z, wr.w};
            #pragma unroll
            for (int a = 0; a < 4; a++)
                #pragma unroll
                for (int b = 0; b < 4; b++)
                    acc[a][b] = fmaf(xv[a], wv[b], acc[a][b]);
        }

        if (c < 7) {
            // Writing the OTHER buffer: safe while peers read `cur`.
            Xs[nxt][xq * 4 + 0][xr] = px.x;  Xs[nxt][xq * 4 + 1][xr] = px.y;
            Xs[nxt][xq * 4 + 2][xr] = px.z;  Xs[nxt][xq * 4 + 3][xr] = px.w;
            Ws[nxt][xq * 4 + 0][xr] = pw.x;  Ws[nxt][xq * 4 + 1][xr] = pw.y;
            Ws[nxt][xq * 4 + 2][xr] = pw.z;  Ws[nxt][xq * 4 + 3][xr] = pw.w;
            __syncthreads();
        }
    }

    #pragma unroll
    for (int a = 0; a < 4; a++) {
        float4 v = make_float4(acc[a][0], acc[a][1], acc[a][2], acc[a][3]);
        *(float4*)&g_Y[(m0 + ty * 4 + a) * O_DIM + o0 + tx * 4] = v;
    }
}

// ---------------------------------------------------------------------------
// Kernel 2: closed-form BN stats. 32 blocks (br, fg) x 512 threads.
// Each 64-thread group owns one t: r0 = 0..15 rows x4, slot = which 4 cols
// (A+0, A+4, B+0, B+4 of the 8-f strip). float4 loads: adjacent lane pairs
// fill 32B sectors. Warp shfl reduce -> per-t sums in smem -> fold
// s = g*rstd, h = b - mean*s. (Measured: part of the 98.8us best config.)
// ---------------------------------------------------------------------------
__global__ void __launch_bounds__(512) stats_kernel(const float* __restrict__ gamma1,
                                                    const float* __restrict__ beta1,
                                                    const float* __restrict__ gamma2,
                                                    const float* __restrict__ beta2) {
    const int bid = blockIdx.x;          // 32 blocks
    const int br = bid >> 4, fg = bid & 15;
    const int fb = fg * 8;
    const int colA = br * 256 + fb;
    const int tid = threadIdx.x;
    const int w = tid >> 5, l = tid & 31;
    const int tw = tid >> 6;             // t this 64-thread group owns
    const int t64 = tid & 63;
    const int r0 = t64 >> 2;             // 0..15
    const int slot = t64 & 3;            // 0:A+0 1:A+4 2:B+0 3:B+4
    const int coff = colA + (slot >> 1) * 128 + (slot & 1) * 4;

    __shared__ float SW[16][16];         // [warp][slot*4+comp] sum partials
    __shared__ float SQ[16][16];         // sum-of-squares partials
    __shared__ float TA[8][8], TB[8][8], QA[8][8], QB[8][8];

    float4 st = make_float4(0.f, 0.f, 0.f, 0.f);
    float4 sq = make_float4(0.f, 0.f, 0.f, 0.f);
    #pragma unroll
    for (int k = 0; k < 16; k++) {
        const int m = tw * 256 + k * 16 + r0;
        const float4 v = *(const float4*)&g_Y[m * O_DIM + coff];
        st.x += v.x;  st.y += v.y;  st.z += v.z;  st.w += v.w;
        sq.x = fmaf(v.x, v.x, sq.x);  sq.y = fmaf(v.y, v.y, sq.y);
        sq.z = fmaf(v.z, v.z, sq.z);  sq.w = fmaf(v.w, v.w, sq.w);
    }
    // reduce over r0 within warp (same-slot lanes are stride 4)
    #pragma unroll
    for (int off = 4; off < 32; off <<= 1) {
        st.x += __shfl_xor_sync(0xffffffffu, st.x, off);
        st.y += __shfl_xor_sync(0xffffffffu, st.y, off);
        st.z += __shfl_xor_sync(0xffffffffu, st.z, off);
        st.w += __shfl_xor_sync(0xffffffffu, st.w, off);
        sq.x += __shfl_xor_sync(0xffffffffu, sq.x, off);
        sq.y += __shfl_xor_sync(0xffffffffu, sq.y, off);
        sq.z += __shfl_xor_sync(0xffffffffu, sq.z, off);
        sq.w += __shfl_xor_sync(0xffffffffu, sq.w, off);
    }
    if (l < 4) {                          // lane l holds slot l
        SW[w][l * 4 + 0] = st.x;  SW[w][l * 4 + 1] = st.y;
        SW[w][l * 4 + 2] = st.z;  SW[w][l * 4 + 3] = st.w;
        SQ[w][l * 4 + 0] = sq.x;  SQ[w][l * 4 + 1] = sq.y;
        SQ[w][l * 4 + 2] = sq.z;  SQ[w][l * 4 + 3] = sq.w;
    }
    __syncthreads();

    // combine the two warps of each t-group (t uses warps 2t, 2t+1)
    if (tid < 64) {
        const int t = tid >> 3, fi = tid & 7;
        const int sl = fi >> 2, cp = fi & 3;
        TA[t][fi] = SW[2 * t][sl * 4 + cp]       + SW[2 * t + 1][sl * 4 + cp];
        TB[t][fi] = SW[2 * t][(2 + sl) * 4 + cp] + SW[2 * t + 1][(2 + sl) * 4 + cp];
        QA[t][fi] = SQ[2 * t][sl * 4 + cp]       + SQ[2 * t + 1][sl * 4 + cp];
        QB[t][fi] = SQ[2 * t][(2 + sl) * 4 + cp] + SQ[2 * t + 1][(2 + sl) * 4 + cp];
    }
    __syncthreads();

    if (tid < 8) {
        const int fi = tid;
        float sumA = 0.f, sumB = 0.f, cross = 0.f, sqA = 0.f, sqB = 0.f;
        #pragma unroll
        for (int t = 0; t < 8; t++) {
            const float a = TA[t][fi], b = TB[t][fi];
            sumA += a;  sumB += b;  cross = fmaf(a, b, cross);
            sqA += QA[t][fi];  sqB += QB[t][fi];
        }
        const float mean = (sumA + sumB) * (1.0f / 2048.0f);
        const float ey2  = (256.0f * (sqA + sqB) + 2.0f * cross) * (1.0f / 524288.0f);
        const float var  = ey2 - mean * mean;
        const int fglob = fb + fi;
        const float g  = br ? gamma2[fglob] : gamma1[fglob];
        const float bb = br ? beta2[fglob]  : beta1[fglob];
        const float s  = g * rsqrtf(var + 1e-5f);
        g_sh[br * 256 + fglob]       = s;
        g_sh[br * 256 + 128 + fglob] = bb - mean * s;
    }
}

// ---------------------------------------------------------------------------
// Kernel 3: streaming epilogue (write-bound, 537 MB).
// 2048 blocks x 128 threads: block = (t, br, 8-row i-tile, j-quarter);
// 2048/148 = 13.8 blocks/SM -> ~1% wave tail. Warp w handles 16 j's;
// j OUTER, i inner: each b4 load reused for 8 i-rows, p[ii]=fma(a,s,h)
// in registers. Streaming stores (__stcs).
// ---------------------------------------------------------------------------
__global__ void __launch_bounds__(128) edge_kernel(float* __restrict__ out) {
    const int bid = blockIdx.x;          // 2048 blocks
    const int jq = bid & 3;
    const int itile = (bid >> 2) & 31;
    const int br = (bid >> 7) & 1;
    const int t = bid >> 8;
    const int i0 = itile * 8;
    const int tid = threadIdx.x;
    const int w = tid >> 5, l = tid & 31;
    const int f0 = l * 4;
    const int j0 = jq * 64 + w * 16;

    const float4 s4 = *(const float4*)&g_sh[br * 256 + f0];
    const float4 h4 = *(const float4*)&g_sh[br * 256 + 128 + f0];
    const int baseA = br * 256 + f0;
    const int baseB = baseA + 128;

    float4 p[8];
    #pragma unroll
    for (int ii = 0; ii < 8; ii++) {
        const float4 a4 = *(const float4*)&g_Y[(t * 256 + i0 + ii) * O_DIM + baseA];
        p[ii].x = fmaf(a4.x, s4.x, h4.x);
        p[ii].y = fmaf(a4.y, s4.y, h4.y);
        p[ii].z = fmaf(a4.z, s4.z, h4.z);
        p[ii].w = fmaf(a4.w, s4.w, h4.w);
    }

    // out index: (((t*2+br)*256 + i) * 256 + j) * 128 + f
    const size_t outbase = (size_t)((t * 2 + br) * 256 + i0) * (256 * 128);

    #pragma unroll 2
    for (int jj = 0; jj < 16; jj++) {
        const int j = j0 + jj;
        const float4 b4 = *(const float4*)&g_Y[(t * 256 + j) * O_DIM + baseB];
        float* orow = out + outbase + (size_t)j * 128 + f0;
        #pragma unroll
        for (int ii = 0; ii < 8; ii++) {
            float vx = fmaxf(fmaf(b4.x, s4.x, p[ii].x), 0.0f);
            float vy = fmaxf(fmaf(b4.y, s4.y, p[ii].y), 0.0f);
            float vz = fmaxf(fmaf(b4.z, s4.z, p[ii].z), 0.0f);
            float vw = fmaxf(fmaf(b4.w, s4.w, p[ii].w), 0.0f);
            if (j == i0 + ii) { vx = 0.f; vy = 0.f; vz = 0.f; vw = 0.f; }
            float sm = (vx + vy) + (vz + vw);
            #pragma unroll
            for (int off = 16; off; off >>= 1)
                sm += __shfl_xor_sync(0xffffffffu, sm, off);
            const float inv = __fdividef(1.0f, fmaxf(sm, 1e-12f));
            float4 o4 = make_float4(vx * inv, vy * inv, vz * inv, vw * inv);
            __stcs((float4*)(orow + (size_t)ii * (256 * 128)), o4);
        }
    }
}

// ---------------------------------------------------------------------------
extern "C" void kernel_launch(void* const* d_in, const int* in_sizes, int n_in,
                              void* d_out, int out_size) {
    const float* x  = (const float*)d_in[0];   // node_feats [8,256,128]
    const float* w1 = (const float*)d_in[1];   // [128,256]
    const float* g1 = (const float*)d_in[2];
    const float* b1 = (const float*)d_in[3];
    const float* w2 = (const float*)d_in[4];
    const float* g2 = (const float*)d_in[5];
    const float* b2 = (const float*)d_in[6];
    float* out = (float*)d_out;                // [8,2,256,256,128] fp32

    dim3 ggrid(O_DIM / 64, M_DIM / 64);        // (8, 32) = 256 blocks
    gemm_kernel<<<ggrid, 256>>>(x, w1, w2);
    stats_kernel<<<32, 512>>>(g1, b1, g2, b2);
    edge_kernel<<<2048, 128>>>(out);
}